// round 4
// baseline (speedup 1.0000x reference)
#include <cuda_runtime.h>
#include <cuda_bf16.h>
#include <mma.h>

using namespace nvcuda;

// Problem dims (fixed by reference)
constexpr int BB   = 2;
constexpr int HH   = 16;
constexpr int SS   = 2048;
constexpr int DD   = 64;

constexpr int BR = 64;    // query rows per CTA
constexpr int BC = 128;   // key columns per tile
constexpr int NTHREADS = 256;

// shared-memory leading dims (elements)
constexpr int LDQ  = 72;   // bf16 tiles, mult of 8
constexpr int LDK  = 72;
constexpr int LDV  = 72;
constexpr int LDP  = 136;  // bf16 P tiles
constexpr int LDSS = 132;  // fp32 score/O scratch, mult of 4

// smem layout (bytes): Qh,Ql | Kh,Kl | Vh,Vl | Ph,Pl | Ssm | rowSum
constexpr int SZ_Q  = BR * LDQ * 2;       // 9216
constexpr int SZ_K  = BC * LDK * 2;       // 18432
constexpr int SZ_V  = BC * LDV * 2;       // 18432
constexpr int SZ_P  = BR * LDP * 2;       // 17408
constexpr int SZ_S  = BR * LDSS * 4;      // 33792
constexpr int SMEM_BYTES = 2*SZ_Q + 2*SZ_K + 2*SZ_V + 2*SZ_P + SZ_S + BR*4; // 161024

// g = exp(dwm / sigma^2), broadcast over heads: [B, S, S]
__device__ float g_buf[(size_t)BB * SS * SS];

// ---------------------------------------------------------------------------
// Kernel 1: g = exp(dwm * inv_sigma2), computed ONCE per batch (not per head).
// ---------------------------------------------------------------------------
__global__ void g_kernel(const float* __restrict__ dwm,
                         const float* __restrict__ sigma, int n4)
{
    float sg = sigma[0];
    float inv = 1.0f / (sg * sg);
    int idx    = blockIdx.x * blockDim.x + threadIdx.x;
    int stride = gridDim.x * blockDim.x;
    const float4* in = (const float4*)dwm;
    float4* g4 = (float4*)g_buf;
    for (int i = idx; i < n4; i += stride) {
        float4 d = in[i];
        float4 o;
        o.x = expf(d.x * inv);
        o.y = expf(d.y * inv);
        o.z = expf(d.z * inv);
        o.w = expf(d.w * inv);
        g4[i] = o;
    }
}

// ---------------------------------------------------------------------------
// Kernel 2: flash-style attention, split-bf16 tensor-core matmuls.
// Grid: (S/BR, H, B). One CTA owns 64 query rows for one (b,h).
// ---------------------------------------------------------------------------
__global__ void __launch_bounds__(NTHREADS, 1)
attn_kernel(const float* __restrict__ q, const float* __restrict__ k,
            const float* __restrict__ v, float* __restrict__ out,
            float* __restrict__ attn)
{
    extern __shared__ char smem[];
    __nv_bfloat16* Qh = (__nv_bfloat16*)smem;
    __nv_bfloat16* Ql = Qh + BR * LDQ;
    __nv_bfloat16* Kh = Ql + BR * LDQ;
    __nv_bfloat16* Kl = Kh + BC * LDK;
    __nv_bfloat16* Vh = Kl + BC * LDK;
    __nv_bfloat16* Vl = Vh + BC * LDV;
    __nv_bfloat16* Ph = Vl + BC * LDV;
    __nv_bfloat16* Pl = Ph + BR * LDP;
    float* Ssm    = (float*)(Pl + BR * LDP);
    float* rowSum = Ssm + BR * LDSS;

    const int tid  = threadIdx.x;
    const int warp = tid >> 5;
    const int lane = tid & 31;
    const int b    = blockIdx.z;
    const int h    = blockIdx.y;
    const int row0 = blockIdx.x * BR;
    const size_t bh = (size_t)(b * HH + h);

    const float* qp = q + bh * SS * DD + (size_t)row0 * DD;
    const float* kp = k + bh * SS * DD;
    const float* vp = v + bh * SS * DD;
    const float* gp = g_buf + (size_t)b * SS * SS + (size_t)row0 * SS;
    float* attnp = attn + (bh * SS + row0) * (size_t)SS;
    float* outp  = out  + (bh * SS + row0) * (size_t)DD;

    if (tid < BR) rowSum[tid] = 0.0f;

    // Stage Q (scaled by 1/TEMPERATURE = 0.125), split into bf16 hi/lo.
    for (int i = tid; i < BR * (DD / 4); i += NTHREADS) {
        int r  = i >> 4;            // DD/4 = 16 float4 per row
        int c4 = (i & 15) << 2;
        float4 qv = *(const float4*)(qp + r * DD + c4);
        float vals[4] = {qv.x, qv.y, qv.z, qv.w};
        #pragma unroll
        for (int j = 0; j < 4; j++) {
            float x = vals[j] * 0.125f;
            __nv_bfloat16 hi = __float2bfloat16_rn(x);
            Qh[r * LDQ + c4 + j] = hi;
            Ql[r * LDQ + c4 + j] = __float2bfloat16_rn(x - __bfloat162float(hi));
        }
    }

    // Persistent unnormalized O accumulators: warp covers rows [wr*16, +16),
    // cols [wc*32, +32) as two 16x16 fragments.
    const int wr = warp >> 1;   // 0..3
    const int wc = warp & 1;    // 0..1
    wmma::fragment<wmma::accumulator, 16, 16, 16, float> oacc0, oacc1;
    wmma::fill_fragment(oacc0, 0.0f);
    wmma::fill_fragment(oacc1, 0.0f);

    __syncthreads();

    for (int kt = 0; kt < SS / BC; kt++) {
        const int key0 = kt * BC;

        // ---- Load K,V tile, split into bf16 hi/lo -------------------------
        for (int i = tid; i < BC * (DD / 4); i += NTHREADS) {
            int r  = i >> 4;
            int c4 = (i & 15) << 2;
            float4 kv = *(const float4*)(kp + (size_t)(key0 + r) * DD + c4);
            float4 vv = *(const float4*)(vp + (size_t)(key0 + r) * DD + c4);
            float ka[4] = {kv.x, kv.y, kv.z, kv.w};
            float va[4] = {vv.x, vv.y, vv.z, vv.w};
            #pragma unroll
            for (int j = 0; j < 4; j++) {
                __nv_bfloat16 khi = __float2bfloat16_rn(ka[j]);
                Kh[r * LDK + c4 + j] = khi;
                Kl[r * LDK + c4 + j] = __float2bfloat16_rn(ka[j] - __bfloat162float(khi));
                __nv_bfloat16 vhi = __float2bfloat16_rn(va[j]);
                Vh[r * LDV + c4 + j] = vhi;
                Vl[r * LDV + c4 + j] = __float2bfloat16_rn(va[j] - __bfloat162float(vhi));
            }
        }
        __syncthreads();

        // ---- S = (Q/8) K^T, split-bf16 (qh*kh + qh*kl + ql*kh) ------------
        // Warp tile: 16 rows x 64 cols (4 fragments).
        {
            wmma::fragment<wmma::accumulator, 16, 16, 16, float> sacc[4];
            #pragma unroll
            for (int f = 0; f < 4; f++) wmma::fill_fragment(sacc[f], 0.0f);
            #pragma unroll
            for (int d0 = 0; d0 < DD; d0 += 16) {
                wmma::fragment<wmma::matrix_a, 16, 16, 16, __nv_bfloat16, wmma::row_major> ah, al;
                wmma::load_matrix_sync(ah, Qh + wr * 16 * LDQ + d0, LDQ);
                wmma::load_matrix_sync(al, Ql + wr * 16 * LDQ + d0, LDQ);
                #pragma unroll
                for (int f = 0; f < 4; f++) {
                    int col = wc * 64 + f * 16;
                    wmma::fragment<wmma::matrix_b, 16, 16, 16, __nv_bfloat16, wmma::col_major> bhf, blf;
                    wmma::load_matrix_sync(bhf, Kh + col * LDK + d0, LDK);
                    wmma::load_matrix_sync(blf, Kl + col * LDK + d0, LDK);
                    wmma::mma_sync(sacc[f], ah, bhf, sacc[f]);
                    wmma::mma_sync(sacc[f], ah, blf, sacc[f]);
                    wmma::mma_sync(sacc[f], al, bhf, sacc[f]);
                }
            }
            #pragma unroll
            for (int f = 0; f < 4; f++)
                wmma::store_matrix_sync(Ssm + wr * 16 * LDSS + wc * 64 + f * 16,
                                        sacc[f], LDSS, wmma::mem_row_major);
        }
        __syncthreads();

        // ---- p = exp(|s * g|); write unnormalized attn; split p to bf16 ---
        for (int it = 0; it < BR / 2; it++) {
            int r = it * 2 + (tid >> 7);
            int c = tid & 127;
            float s = Ssm[r * LDSS + c];
            float g = __ldg(gp + (size_t)r * SS + key0 + c);
            float p = __expf(fabsf(s * g));
            Ssm[r * LDSS + c] = p;
            attnp[(size_t)r * SS + key0 + c] = p;   // unnormalized; rescaled in tail
            __nv_bfloat16 phi = __float2bfloat16_rn(p);
            Ph[r * LDP + c] = phi;
            Pl[r * LDP + c] = __float2bfloat16_rn(p - __bfloat162float(phi));
        }
        __syncthreads();

        // ---- row sums: warp w reduces rows w, w+8, ..., w+56 --------------
        #pragma unroll
        for (int rr = 0; rr < BR / 8; rr++) {
            int r = warp + rr * 8;
            float sum = Ssm[r * LDSS + lane]      + Ssm[r * LDSS + lane + 32]
                      + Ssm[r * LDSS + lane + 64] + Ssm[r * LDSS + lane + 96];
            #pragma unroll
            for (int off = 16; off > 0; off >>= 1)
                sum += __shfl_xor_sync(0xffffffffu, sum, off);
            if (lane == 0) rowSum[r] += sum;
        }

        // ---- O += P V, split-bf16 (ph*vh + ph*vl + pl*vh) ------------------
        #pragma unroll
        for (int k0 = 0; k0 < BC; k0 += 16) {
            wmma::fragment<wmma::matrix_a, 16, 16, 16, __nv_bfloat16, wmma::row_major> pah, pal;
            wmma::load_matrix_sync(pah, Ph + wr * 16 * LDP + k0, LDP);
            wmma::load_matrix_sync(pal, Pl + wr * 16 * LDP + k0, LDP);
            {
                int col = wc * 32;
                wmma::fragment<wmma::matrix_b, 16, 16, 16, __nv_bfloat16, wmma::row_major> vbh, vbl;
                wmma::load_matrix_sync(vbh, Vh + k0 * LDV + col, LDV);
                wmma::load_matrix_sync(vbl, Vl + k0 * LDV + col, LDV);
                wmma::mma_sync(oacc0, pah, vbh, oacc0);
                wmma::mma_sync(oacc0, pah, vbl, oacc0);
                wmma::mma_sync(oacc0, pal, vbh, oacc0);
            }
            {
                int col = wc * 32 + 16;
                wmma::fragment<wmma::matrix_b, 16, 16, 16, __nv_bfloat16, wmma::row_major> vbh, vbl;
                wmma::load_matrix_sync(vbh, Vh + k0 * LDV + col, LDV);
                wmma::load_matrix_sync(vbl, Vl + k0 * LDV + col, LDV);
                wmma::mma_sync(oacc1, pah, vbh, oacc1);
                wmma::mma_sync(oacc1, pah, vbl, oacc1);
                wmma::mma_sync(oacc1, pal, vbh, oacc1);
            }
        }
        __syncthreads();
    }

    // ---- normalize + write O -------------------------------------------
    if (tid < BR) rowSum[tid] = 1.0f / rowSum[tid];
    wmma::store_matrix_sync(Ssm + wr * 16 * LDSS + wc * 32,      oacc0, LDSS, wmma::mem_row_major);
    wmma::store_matrix_sync(Ssm + wr * 16 * LDSS + wc * 32 + 16, oacc1, LDSS, wmma::mem_row_major);
    __syncthreads();

    for (int i = tid; i < BR * DD; i += NTHREADS) {
        int r = i >> 6, c = i & 63;
        outp[(size_t)r * DD + c] = Ssm[r * LDSS + c] * rowSum[r];
    }

    // ---- rescale this CTA's attn slice in place (likely L2-resident) ----
    for (int i = tid; i < BR * (SS / 4); i += NTHREADS) {
        int r  = i >> 9;             // SS/4 = 512 float4 per row
        int c4 = (i & 511) << 2;
        float4* p4 = (float4*)(attnp + (size_t)r * SS + c4);
        float4 vv = *p4;
        float inv = rowSum[r];
        vv.x *= inv; vv.y *= inv; vv.z *= inv; vv.w *= inv;
        *p4 = vv;
    }
}

// ---------------------------------------------------------------------------
extern "C" void kernel_launch(void* const* d_in, const int* in_sizes, int n_in,
                              void* d_out, int out_size)
{
    const float* q     = (const float*)d_in[0];
    const float* k     = (const float*)d_in[1];
    const float* v     = (const float*)d_in[2];
    const float* dwm   = (const float*)d_in[3];
    const float* sigma = (const float*)d_in[4];

    float* out  = (float*)d_out;                         // [B,H,S,D]
    float* attn = out + (size_t)BB * HH * SS * DD;       // [B,H,S,S]

    // 1) g = exp(dwm / sigma^2), once per batch element
    g_kernel<<<4096, 256>>>(dwm, sigma, (BB * SS * SS) / 4);

    // 2) fused attention (needs >48KB dynamic smem)
    cudaFuncSetAttribute(attn_kernel, cudaFuncAttributeMaxDynamicSharedMemorySize,
                         SMEM_BYTES);
    dim3 grid(SS / BR, HH, BB);
    attn_kernel<<<grid, NTHREADS, SMEM_BYTES>>>(q, k, v, out, attn);

    (void)in_sizes; (void)n_in; (void)out_size;
}

// round 6
// speedup vs baseline: 1.3999x; 1.3999x over previous
#include <cuda_runtime.h>
#include <cuda_bf16.h>
#include <cstdint>

// Problem dims (fixed by reference)
constexpr int BB = 2;
constexpr int HH = 16;
constexpr int SS = 2048;
constexpr int DD = 64;

constexpr int BR = 64;     // query rows per CTA
constexpr int BC = 128;    // keys per tile
constexpr int NTHREADS = 256;

constexpr int LDK  = 72;           // smem leading dim (bf16 elems), 144B rows
constexpr int TILE = BC * LDK;     // elems per smem tensor buffer (9216)
constexpr int TILEB = TILE * 2;    // bytes (18432)
constexpr int SMEM_BYTES = 8 * TILEB;   // KH[2],KL[2],VH[2],VL[2] = 147456

// g = exp(dwm / sigma^2), broadcast over heads: [B, S, S]
__device__ float g_buf[(size_t)BB * SS * SS];

// ---------------------------------------------------------------------------
__global__ void g_kernel(const float* __restrict__ dwm,
                         const float* __restrict__ sigma, int n4)
{
    float sg = sigma[0];
    float inv = 1.0f / (sg * sg);
    int idx    = blockIdx.x * blockDim.x + threadIdx.x;
    int stride = gridDim.x * blockDim.x;
    const float4* in = (const float4*)dwm;
    float4* g4 = (float4*)g_buf;
    for (int i = idx; i < n4; i += stride) {
        float4 d = in[i];
        float4 o;
        o.x = expf(d.x * inv);
        o.y = expf(d.y * inv);
        o.z = expf(d.z * inv);
        o.w = expf(d.w * inv);
        g4[i] = o;
    }
}

// ---------------------------------------------------------------------------
__device__ __forceinline__ uint32_t pk(__nv_bfloat16 a, __nv_bfloat16 b) {
    return (uint32_t)__bfloat16_as_ushort(a) |
           ((uint32_t)__bfloat16_as_ushort(b) << 16);
}

__device__ __forceinline__ void mma16816(float* c, const uint32_t* a, const uint32_t* b) {
    asm volatile(
        "mma.sync.aligned.m16n8k16.row.col.f32.bf16.bf16.f32 "
        "{%0,%1,%2,%3}, {%4,%5,%6,%7}, {%8,%9}, {%0,%1,%2,%3};\n"
        : "+f"(c[0]), "+f"(c[1]), "+f"(c[2]), "+f"(c[3])
        : "r"(a[0]), "r"(a[1]), "r"(a[2]), "r"(a[3]), "r"(b[0]), "r"(b[1]));
}

__device__ __forceinline__ void ldsm4(uint32_t& r0, uint32_t& r1, uint32_t& r2,
                                      uint32_t& r3, uint32_t addr) {
    asm volatile("ldmatrix.sync.aligned.m8n8.x4.shared.b16 {%0,%1,%2,%3},[%4];\n"
                 : "=r"(r0), "=r"(r1), "=r"(r2), "=r"(r3) : "r"(addr));
}
__device__ __forceinline__ void ldsm4t(uint32_t& r0, uint32_t& r1, uint32_t& r2,
                                       uint32_t& r3, uint32_t addr) {
    asm volatile("ldmatrix.sync.aligned.m8n8.x4.trans.shared.b16 {%0,%1,%2,%3},[%4];\n"
                 : "=r"(r0), "=r"(r1), "=r"(r2), "=r"(r3) : "r"(addr));
}

// ---------------------------------------------------------------------------
// Register-resident flash attention, split-bf16 mma.sync.
// Grid (S/BR, H, B), 256 threads. Warp (wr=warp>>2, wc=warp&3):
//   S tile per warp: rows [wr*32, +32), keys [wc*32, +32)
//   O partial per warp: rows [wr*32, +32) x full D=64, over its own 32 keys.
// ---------------------------------------------------------------------------
__global__ void __launch_bounds__(NTHREADS, 1)
attn_kernel(const float* __restrict__ q, const float* __restrict__ k,
            const float* __restrict__ v, float* __restrict__ out,
            float* __restrict__ attn)
{
    extern __shared__ __align__(16) char smem_raw[];
    __nv_bfloat16* KH = (__nv_bfloat16*)smem_raw;       // [2][BC][LDK]
    __nv_bfloat16* KL = KH + 2 * TILE;
    __nv_bfloat16* VH = KH + 4 * TILE;
    __nv_bfloat16* VL = KH + 6 * TILE;

    const int tid  = threadIdx.x;
    const int warp = tid >> 5;
    const int lane = tid & 31;
    const int gID  = lane >> 2;     // group id 0..7
    const int tig  = lane & 3;      // thread in group
    const int wr   = warp >> 2;     // 0..1 (row half)
    const int wc   = warp & 3;      // 0..3 (key quarter)
    const int b    = blockIdx.z;
    const int h    = blockIdx.y;
    const int row0 = blockIdx.x * BR;
    const size_t bh = (size_t)(b * HH + h);

    const float* qp = q + bh * SS * DD + (size_t)row0 * DD;
    const float* kp = k + bh * SS * DD;
    const float* vp = v + bh * SS * DD;
    const float* gp = g_buf + (size_t)b * SS * SS + (size_t)row0 * SS;
    float* attnp = attn + (bh * SS + row0) * (size_t)SS;
    float* outp  = out  + (bh * SS + row0) * (size_t)DD;

    // ---- Q fragments (scaled by 1/8), hi/lo split, persistent in regs ------
    uint32_t qh[2][4][4], ql[2][4][4];
    {
        const int rA0 = wr * 32 + gID;
        #pragma unroll
        for (int mt = 0; mt < 2; mt++) {
            const float* r0p = qp + (size_t)(rA0 + mt * 16) * DD;
            const float* r1p = r0p + 8 * DD;
            #pragma unroll
            for (int ks = 0; ks < 4; ks++) {
                int c = ks * 16 + tig * 2;
                float2 xs[4];
                xs[0] = *(const float2*)(r0p + c);
                xs[1] = *(const float2*)(r1p + c);
                xs[2] = *(const float2*)(r0p + c + 8);
                xs[3] = *(const float2*)(r1p + c + 8);
                #pragma unroll
                for (int j = 0; j < 4; j++) {
                    float ax = xs[j].x * 0.125f, ay = xs[j].y * 0.125f;
                    __nv_bfloat16 hx = __float2bfloat16_rn(ax);
                    __nv_bfloat16 hy = __float2bfloat16_rn(ay);
                    qh[mt][ks][j] = pk(hx, hy);
                    ql[mt][ks][j] = pk(__float2bfloat16_rn(ax - __bfloat162float(hx)),
                                       __float2bfloat16_rn(ay - __bfloat162float(hy)));
                }
            }
        }
    }

    // ---- ldmatrix per-lane address components ------------------------------
    const uint32_t kh_s = (uint32_t)__cvta_generic_to_shared(KH);
    const uint32_t kl_s = (uint32_t)__cvta_generic_to_shared(KL);
    const uint32_t vh_s = (uint32_t)__cvta_generic_to_shared(VH);
    const uint32_t vl_s = (uint32_t)__cvta_generic_to_shared(VL);
    // QK B frags (non-trans): lanes 0-7/8-15 -> ntile 2p d-lo/d-hi, 16-31 -> ntile 2p+1
    const int keyc  = wc * 32 + ((lane >> 4) & 1) * 8 + (lane & 7);
    const int dsel  = ((lane >> 3) & 1) * 8;
    const uint32_t koff = (uint32_t)(keyc * LDK + dsel) * 2;
    // PV B frags (trans): lanes 0-7/8-15 -> keys +0/+8 at d-tile 2dp, 16-31 -> d-tile 2dp+1
    const int vkeyc = wc * 32 + ((lane >> 3) & 1) * 8 + (lane & 7);
    const int vdsel = ((lane >> 4) & 1) * 8;
    const uint32_t voff = (uint32_t)(vkeyc * LDK + vdsel) * 2;

    // KV loader thread mapping: row = tid>>1, d-half = (tid&1)*32
    const int lr  = tid >> 1;
    const int ld0 = (tid & 1) * 32;

    float oacc[2][8][4];
    #pragma unroll
    for (int mt = 0; mt < 2; mt++)
        #pragma unroll
        for (int dt = 0; dt < 8; dt++)
            #pragma unroll
            for (int j = 0; j < 4; j++) oacc[mt][dt][j] = 0.0f;

    float rs[4] = {0.0f, 0.0f, 0.0f, 0.0f};   // rowsum partials

    float4 kreg[8], vreg[8];

    // ---- prologue: tile 0 into buffer 0 ------------------------------------
    {
        const float* kb = kp + (size_t)lr * DD + ld0;
        const float* vb = vp + (size_t)lr * DD + ld0;
        #pragma unroll
        for (int j = 0; j < 8; j++) {
            kreg[j] = *(const float4*)(kb + 4 * j);
            vreg[j] = *(const float4*)(vb + 4 * j);
        }
        __nv_bfloat16* khp = KH + lr * LDK + ld0;
        __nv_bfloat16* klp = KL + lr * LDK + ld0;
        __nv_bfloat16* vhp = VH + lr * LDK + ld0;
        __nv_bfloat16* vlp = VL + lr * LDK + ld0;
        #pragma unroll
        for (int j = 0; j < 8; j++) {
            float4 x = kreg[j];
            __nv_bfloat16 h0 = __float2bfloat16_rn(x.x), h1 = __float2bfloat16_rn(x.y);
            __nv_bfloat16 h2 = __float2bfloat16_rn(x.z), h3 = __float2bfloat16_rn(x.w);
            uint2 hv = {pk(h0, h1), pk(h2, h3)};
            uint2 lv = {pk(__float2bfloat16_rn(x.x - __bfloat162float(h0)),
                           __float2bfloat16_rn(x.y - __bfloat162float(h1))),
                        pk(__float2bfloat16_rn(x.z - __bfloat162float(h2)),
                           __float2bfloat16_rn(x.w - __bfloat162float(h3)))};
            *(uint2*)(khp + 4 * j) = hv;
            *(uint2*)(klp + 4 * j) = lv;
            float4 y = vreg[j];
            __nv_bfloat16 g0 = __float2bfloat16_rn(y.x), g1 = __float2bfloat16_rn(y.y);
            __nv_bfloat16 g2 = __float2bfloat16_rn(y.z), g3 = __float2bfloat16_rn(y.w);
            uint2 hv2 = {pk(g0, g1), pk(g2, g3)};
            uint2 lv2 = {pk(__float2bfloat16_rn(y.x - __bfloat162float(g0)),
                            __float2bfloat16_rn(y.y - __bfloat162float(g1))),
                         pk(__float2bfloat16_rn(y.z - __bfloat162float(g2)),
                            __float2bfloat16_rn(y.w - __bfloat162float(g3)))};
            *(uint2*)(vhp + 4 * j) = hv2;
            *(uint2*)(vlp + 4 * j) = lv2;
        }
    }
    __syncthreads();

    // ---- main loop over key tiles ------------------------------------------
    for (int t = 0; t < SS / BC; t++) {
        const int buf  = t & 1;
        const int nbuf = buf ^ 1;
        const int key0 = t * BC;
        const uint32_t bufB = (uint32_t)buf * TILEB;

        // prefetch K(t+1) into regs (latency hidden under QK mmas)
        if (t + 1 < SS / BC) {
            const float* kb = kp + (size_t)(key0 + BC + lr) * DD + ld0;
            #pragma unroll
            for (int j = 0; j < 8; j++) kreg[j] = *(const float4*)(kb + 4 * j);
        }

        // ---- S = (Q/8) K^T : 3-term split-bf16 -----------------------------
        float sacc[2][4][4];
        #pragma unroll
        for (int mt = 0; mt < 2; mt++)
            #pragma unroll
            for (int nt = 0; nt < 4; nt++)
                #pragma unroll
                for (int j = 0; j < 4; j++) sacc[mt][nt][j] = 0.0f;

        #pragma unroll
        for (int ks = 0; ks < 4; ks++) {
            uint32_t Bh[4][2], Bl[4][2];
            #pragma unroll
            for (int p = 0; p < 2; p++) {
                uint32_t off = bufB + koff + (uint32_t)((p * 16 * LDK + ks * 16) * 2);
                ldsm4(Bh[2 * p][0], Bh[2 * p][1], Bh[2 * p + 1][0], Bh[2 * p + 1][1], kh_s + off);
                ldsm4(Bl[2 * p][0], Bl[2 * p][1], Bl[2 * p + 1][0], Bl[2 * p + 1][1], kl_s + off);
            }
            #pragma unroll
            for (int nt = 0; nt < 4; nt++)
                #pragma unroll
                for (int mt = 0; mt < 2; mt++) {
                    mma16816(sacc[mt][nt], qh[mt][ks], Bh[nt]);
                    mma16816(sacc[mt][nt], qh[mt][ks], Bl[nt]);
                    mma16816(sacc[mt][nt], ql[mt][ks], Bh[nt]);
                }
        }

        // store K(t+1) into back buffer; prefetch V(t+1)
        if (t + 1 < SS / BC) {
            __nv_bfloat16* khp = KH + nbuf * TILE + lr * LDK + ld0;
            __nv_bfloat16* klp = KL + nbuf * TILE + lr * LDK + ld0;
            #pragma unroll
            for (int j = 0; j < 8; j++) {
                float4 x = kreg[j];
                __nv_bfloat16 h0 = __float2bfloat16_rn(x.x), h1 = __float2bfloat16_rn(x.y);
                __nv_bfloat16 h2 = __float2bfloat16_rn(x.z), h3 = __float2bfloat16_rn(x.w);
                uint2 hv = {pk(h0, h1), pk(h2, h3)};
                uint2 lv = {pk(__float2bfloat16_rn(x.x - __bfloat162float(h0)),
                               __float2bfloat16_rn(x.y - __bfloat162float(h1))),
                            pk(__float2bfloat16_rn(x.z - __bfloat162float(h2)),
                               __float2bfloat16_rn(x.w - __bfloat162float(h3)))};
                *(uint2*)(khp + 4 * j) = hv;
                *(uint2*)(klp + 4 * j) = lv;
            }
            const float* vb = vp + (size_t)(key0 + BC + lr) * DD + ld0;
            #pragma unroll
            for (int j = 0; j < 8; j++) vreg[j] = *(const float4*)(vb + 4 * j);
        }

        // ---- p = exp(|s*g|) in registers; write unnormalized attn; pack P --
        uint32_t ph[2][2][4], pl[2][2][4];
        #pragma unroll
        for (int mt = 0; mt < 2; mt++) {
            const int rA = wr * 32 + mt * 16 + gID;
            const int rB = rA + 8;
            #pragma unroll
            for (int nt = 0; nt < 4; nt++) {
                const int cg = key0 + wc * 32 + nt * 8 + tig * 2;
                float2 gA = *(const float2*)(gp + (size_t)rA * SS + cg);
                float2 gB = *(const float2*)(gp + (size_t)rB * SS + cg);
                float p0 = __expf(fabsf(sacc[mt][nt][0] * gA.x));
                float p1 = __expf(fabsf(sacc[mt][nt][1] * gA.y));
                float p2 = __expf(fabsf(sacc[mt][nt][2] * gB.x));
                float p3 = __expf(fabsf(sacc[mt][nt][3] * gB.y));
                *(float2*)(attnp + (size_t)rA * SS + cg) = make_float2(p0, p1);
                *(float2*)(attnp + (size_t)rB * SS + cg) = make_float2(p2, p3);
                rs[mt * 2 + 0] += p0 + p1;
                rs[mt * 2 + 1] += p2 + p3;
                __nv_bfloat16 b0 = __float2bfloat16_rn(p0), b1 = __float2bfloat16_rn(p1);
                __nv_bfloat16 b2 = __float2bfloat16_rn(p2), b3 = __float2bfloat16_rn(p3);
                const int kt = nt >> 1, hf = nt & 1;
                ph[mt][kt][hf * 2 + 0] = pk(b0, b1);
                ph[mt][kt][hf * 2 + 1] = pk(b2, b3);
                pl[mt][kt][hf * 2 + 0] = pk(__float2bfloat16_rn(p0 - __bfloat162float(b0)),
                                            __float2bfloat16_rn(p1 - __bfloat162float(b1)));
                pl[mt][kt][hf * 2 + 1] = pk(__float2bfloat16_rn(p2 - __bfloat162float(b2)),
                                            __float2bfloat16_rn(p3 - __bfloat162float(b3)));
            }
        }

        // ---- O += P V over this warp's 32 keys, 3-term split-bf16 ----------
        #pragma unroll
        for (int kt = 0; kt < 2; kt++) {
            #pragma unroll
            for (int dp = 0; dp < 4; dp++) {
                uint32_t off = bufB + voff + (uint32_t)((kt * 16 * LDK + dp * 16) * 2);
                uint32_t Vh0[2], Vh1[2], Vl0[2], Vl1[2];
                ldsm4t(Vh0[0], Vh0[1], Vh1[0], Vh1[1], vh_s + off);
                ldsm4t(Vl0[0], Vl0[1], Vl1[0], Vl1[1], vl_s + off);
                #pragma unroll
                for (int mt = 0; mt < 2; mt++) {
                    mma16816(oacc[mt][2 * dp], ph[mt][kt], Vh0);
                    mma16816(oacc[mt][2 * dp], ph[mt][kt], Vl0);
                    mma16816(oacc[mt][2 * dp], pl[mt][kt], Vh0);
                    mma16816(oacc[mt][2 * dp + 1], ph[mt][kt], Vh1);
                    mma16816(oacc[mt][2 * dp + 1], ph[mt][kt], Vl1);
                    mma16816(oacc[mt][2 * dp + 1], pl[mt][kt], Vh1);
                }
            }
        }

        // store V(t+1) into back buffer
        if (t + 1 < SS / BC) {
            __nv_bfloat16* vhp = VH + nbuf * TILE + lr * LDK + ld0;
            __nv_bfloat16* vlp = VL + nbuf * TILE + lr * LDK + ld0;
            #pragma unroll
            for (int j = 0; j < 8; j++) {
                float4 y = vreg[j];
                __nv_bfloat16 g0 = __float2bfloat16_rn(y.x), g1 = __float2bfloat16_rn(y.y);
                __nv_bfloat16 g2 = __float2bfloat16_rn(y.z), g3 = __float2bfloat16_rn(y.w);
                uint2 hv = {pk(g0, g1), pk(g2, g3)};
                uint2 lv = {pk(__float2bfloat16_rn(y.x - __bfloat162float(g0)),
                               __float2bfloat16_rn(y.y - __bfloat162float(g1))),
                            pk(__float2bfloat16_rn(y.z - __bfloat162float(g2)),
                               __float2bfloat16_rn(y.w - __bfloat162float(g3)))};
                *(uint2*)(vhp + 4 * j) = hv;
                *(uint2*)(vlp + 4 * j) = lv;
            }
        }

        __syncthreads();
    }

    // ---- epilogue: combine partial O, rowsums, normalize --------------------
    // scratch overlays the K/V buffers (safe after final sync)
    float* Ob       = (float*)smem_raw;            // [4][64][68]
    float* rowSumSm = Ob + 4 * 64 * 68;
    float* invS     = rowSumSm + 64;

    if (tid < BR) rowSumSm[tid] = 0.0f;
    __syncthreads();

    // rowsum: reduce over the 4 lanes of each group, then across wc warps
    #pragma unroll
    for (int i = 0; i < 4; i++) {
        rs[i] += __shfl_xor_sync(0xffffffffu, rs[i], 1);
        rs[i] += __shfl_xor_sync(0xffffffffu, rs[i], 2);
    }
    if (tig == 0) {
        atomicAdd(&rowSumSm[wr * 32 + gID],      rs[0]);
        atomicAdd(&rowSumSm[wr * 32 + gID + 8],  rs[1]);
        atomicAdd(&rowSumSm[wr * 32 + gID + 16], rs[2]);
        atomicAdd(&rowSumSm[wr * 32 + gID + 24], rs[3]);
    }

    // each wc warp dumps its partial O (no atomics; disjoint rows per wr)
    {
        float* ObW = Ob + wc * (64 * 68);
        #pragma unroll
        for (int mt = 0; mt < 2; mt++) {
            const int r = wr * 32 + mt * 16 + gID;
            #pragma unroll
            for (int dt = 0; dt < 8; dt++) {
                const int c = dt * 8 + tig * 2;
                *(float2*)&ObW[r * 68 + c]       = make_float2(oacc[mt][dt][0], oacc[mt][dt][1]);
                *(float2*)&ObW[(r + 8) * 68 + c] = make_float2(oacc[mt][dt][2], oacc[mt][dt][3]);
            }
        }
    }
    __syncthreads();

    if (tid < BR) invS[tid] = 1.0f / rowSumSm[tid];
    __syncthreads();

    // output = (sum of 4 partials) * invRowSum
    for (int i = tid; i < BR * DD; i += NTHREADS) {
        const int r = i >> 6, c = i & 63;
        float o = Ob[0 * 4352 + r * 68 + c] + Ob[1 * 4352 + r * 68 + c] +
                  Ob[2 * 4352 + r * 68 + c] + Ob[3 * 4352 + r * 68 + c];
        outp[(size_t)r * DD + c] = o * invS[r];
    }

    // rescale this CTA's attn slice in place (mostly L2-resident)
    for (int i = tid; i < BR * (SS / 4); i += NTHREADS) {
        const int r  = i >> 9;
        const int c4 = (i & 511) << 2;
        float4* p4 = (float4*)(attnp + (size_t)r * SS + c4);
        float4 vv = *p4;
        const float inv = invS[r];
        vv.x *= inv; vv.y *= inv; vv.z *= inv; vv.w *= inv;
        *p4 = vv;
    }
}

// ---------------------------------------------------------------------------
extern "C" void kernel_launch(void* const* d_in, const int* in_sizes, int n_in,
                              void* d_out, int out_size)
{
    const float* q     = (const float*)d_in[0];
    const float* k     = (const float*)d_in[1];
    const float* v     = (const float*)d_in[2];
    const float* dwm   = (const float*)d_in[3];
    const float* sigma = (const float*)d_in[4];

    float* out  = (float*)d_out;                       // [B,H,S,D]
    float* attn = out + (size_t)BB * HH * SS * DD;     // [B,H,S,S]

    g_kernel<<<4096, 256>>>(dwm, sigma, (BB * SS * SS) / 4);

    cudaFuncSetAttribute(attn_kernel, cudaFuncAttributeMaxDynamicSharedMemorySize,
                         SMEM_BYTES);
    dim3 grid(SS / BR, HH, BB);
    attn_kernel<<<grid, NTHREADS, SMEM_BYTES>>>(q, k, v, out, attn);

    (void)in_sizes; (void)n_in; (void)out_size;
}

// round 7
// speedup vs baseline: 2.0387x; 1.4563x over previous
#include <cuda_runtime.h>
#include <cuda_bf16.h>
#include <cstdint>

// Problem dims (fixed by reference)
constexpr int BB = 2;
constexpr int HH = 16;
constexpr int SS = 2048;
constexpr int DD = 64;

constexpr int BR = 64;        // query rows per CTA
constexpr int BC = 64;        // keys per tile
constexpr int NTILES = SS / BC;   // 32
constexpr int NTHREADS = 256;

constexpr int LDK = 72;                 // smem leading dim (bf16), 144B rows
constexpr int QTILE = BR * LDK;         // 4608 elems
constexpr int KTILE = BC * LDK;         // 4608 elems
// smem (bf16 elems): Qh | Ql | KH[2] | KL[2] | VH[2] | VL[2]
constexpr int OFF_QH = 0;
constexpr int OFF_QL = QTILE;
constexpr int OFF_KV = 2 * QTILE;       // 9216
constexpr int SMEM_ELEMS = OFF_KV + 8 * KTILE;   // 46080
constexpr int SMEM_BYTES = SMEM_ELEMS * 2;       // 92160 -> 2 CTAs/SM

constexpr size_t KVELEMS = (size_t)BB * HH * SS * DD;   // 4 Mi

// Precomputed tensors
__device__ float g_buf[(size_t)BB * SS * SS];           // exp(dwm/sigma^2), [B,S,S]
__device__ __nv_bfloat16 KHg[KVELEMS];
__device__ __nv_bfloat16 KLg[KVELEMS];
__device__ __nv_bfloat16 VHg[KVELEMS];
__device__ __nv_bfloat16 VLg[KVELEMS];

// ---------------------------------------------------------------------------
__global__ void g_kernel(const float* __restrict__ dwm,
                         const float* __restrict__ sigma, int n4)
{
    float sg = sigma[0];
    float inv = 1.0f / (sg * sg);
    int idx    = blockIdx.x * blockDim.x + threadIdx.x;
    int stride = gridDim.x * blockDim.x;
    const float4* in = (const float4*)dwm;
    float4* g4 = (float4*)g_buf;
    for (int i = idx; i < n4; i += stride) {
        float4 d = in[i];
        float4 o;
        o.x = expf(d.x * inv);
        o.y = expf(d.y * inv);
        o.z = expf(d.z * inv);
        o.w = expf(d.w * inv);
        g4[i] = o;
    }
}

// ---------------------------------------------------------------------------
__device__ __forceinline__ uint32_t pk(__nv_bfloat16 a, __nv_bfloat16 b) {
    return (uint32_t)__bfloat16_as_ushort(a) |
           ((uint32_t)__bfloat16_as_ushort(b) << 16);
}

// Split K,V (fp32) into hi/lo bf16 global tensors, once.
__global__ void kvsplit_kernel(const float* __restrict__ k,
                               const float* __restrict__ v, int n4)
{
    int idx    = blockIdx.x * blockDim.x + threadIdx.x;
    int stride = gridDim.x * blockDim.x;
    const float4* k4 = (const float4*)k;
    const float4* v4 = (const float4*)v;
    uint2* kh = (uint2*)KHg; uint2* kl = (uint2*)KLg;
    uint2* vh = (uint2*)VHg; uint2* vl = (uint2*)VLg;
    for (int i = idx; i < n4; i += stride) {
        float4 x = k4[i];
        __nv_bfloat16 h0 = __float2bfloat16_rn(x.x), h1 = __float2bfloat16_rn(x.y);
        __nv_bfloat16 h2 = __float2bfloat16_rn(x.z), h3 = __float2bfloat16_rn(x.w);
        kh[i] = make_uint2(pk(h0, h1), pk(h2, h3));
        kl[i] = make_uint2(pk(__float2bfloat16_rn(x.x - __bfloat162float(h0)),
                              __float2bfloat16_rn(x.y - __bfloat162float(h1))),
                           pk(__float2bfloat16_rn(x.z - __bfloat162float(h2)),
                              __float2bfloat16_rn(x.w - __bfloat162float(h3))));
        float4 y = v4[i];
        __nv_bfloat16 g0 = __float2bfloat16_rn(y.x), g1 = __float2bfloat16_rn(y.y);
        __nv_bfloat16 g2 = __float2bfloat16_rn(y.z), g3 = __float2bfloat16_rn(y.w);
        vh[i] = make_uint2(pk(g0, g1), pk(g2, g3));
        vl[i] = make_uint2(pk(__float2bfloat16_rn(y.x - __bfloat162float(g0)),
                              __float2bfloat16_rn(y.y - __bfloat162float(g1))),
                           pk(__float2bfloat16_rn(y.z - __bfloat162float(g2)),
                              __float2bfloat16_rn(y.w - __bfloat162float(g3))));
    }
}

// ---------------------------------------------------------------------------
__device__ __forceinline__ void mma16816(float* c, const uint32_t* a, const uint32_t* b) {
    asm volatile(
        "mma.sync.aligned.m16n8k16.row.col.f32.bf16.bf16.f32 "
        "{%0,%1,%2,%3}, {%4,%5,%6,%7}, {%8,%9}, {%0,%1,%2,%3};\n"
        : "+f"(c[0]), "+f"(c[1]), "+f"(c[2]), "+f"(c[3])
        : "r"(a[0]), "r"(a[1]), "r"(a[2]), "r"(a[3]), "r"(b[0]), "r"(b[1]));
}
__device__ __forceinline__ void ldsm4(uint32_t& r0, uint32_t& r1, uint32_t& r2,
                                      uint32_t& r3, uint32_t addr) {
    asm volatile("ldmatrix.sync.aligned.m8n8.x4.shared.b16 {%0,%1,%2,%3},[%4];\n"
                 : "=r"(r0), "=r"(r1), "=r"(r2), "=r"(r3) : "r"(addr));
}
__device__ __forceinline__ void ldsm4t(uint32_t& r0, uint32_t& r1, uint32_t& r2,
                                       uint32_t& r3, uint32_t addr) {
    asm volatile("ldmatrix.sync.aligned.m8n8.x4.trans.shared.b16 {%0,%1,%2,%3},[%4];\n"
                 : "=r"(r0), "=r"(r1), "=r"(r2), "=r"(r3) : "r"(addr));
}
__device__ __forceinline__ void cpa16(uint32_t dst, const void* src) {
    asm volatile("cp.async.cg.shared.global [%0], [%1], 16;\n"
                 :: "r"(dst), "l"(src));
}

// ---------------------------------------------------------------------------
// Flash attention, split-bf16 mma.sync, 2 CTAs/SM.
// Grid (S/BR, H, B), 256 threads. Warp w: wr=w>>1 (row-16 block 0..3),
// wc=w&1 (key-32 half). S tile/warp: 16 rows x 32 keys; O partial 16x64.
// ---------------------------------------------------------------------------
__global__ void __launch_bounds__(NTHREADS, 2)
attn_kernel(const float* __restrict__ q, float* __restrict__ out,
            float* __restrict__ attn)
{
    extern __shared__ __align__(128) char smem_raw[];
    __nv_bfloat16* smB = (__nv_bfloat16*)smem_raw;

    const int tid  = threadIdx.x;
    const int warp = tid >> 5;
    const int lane = tid & 31;
    const int gID  = lane >> 2;
    const int tig  = lane & 3;
    const int wr   = warp >> 1;       // 0..3
    const int wc   = warp & 1;        // 0..1
    const int b    = blockIdx.z;
    const int h    = blockIdx.y;
    const int row0 = blockIdx.x * BR;
    const size_t bh = (size_t)(b * HH + h);

    const float* qp = q + bh * SS * DD + (size_t)row0 * DD;
    const float* gp = g_buf + (size_t)b * SS * SS + (size_t)row0 * SS;
    float* attnp = attn + (bh * SS + row0) * (size_t)SS;
    float* outp  = out  + (bh * SS + row0) * (size_t)DD;

    // ---- stage Q (x 1/8) hi/lo into smem -----------------------------------
    for (int i = tid; i < BR * (DD / 4); i += NTHREADS) {
        int r  = i >> 4;
        int c4 = (i & 15) << 2;
        float4 qv = *(const float4*)(qp + r * DD + c4);
        float vals[4] = {qv.x, qv.y, qv.z, qv.w};
        #pragma unroll
        for (int j = 0; j < 4; j++) {
            float x = vals[j] * 0.125f;
            __nv_bfloat16 hi = __float2bfloat16_rn(x);
            smB[OFF_QH + r * LDK + c4 + j] = hi;
            smB[OFF_QL + r * LDK + c4 + j] =
                __float2bfloat16_rn(x - __bfloat162float(hi));
        }
    }

    // ---- smem addresses -----------------------------------------------------
    const uint32_t sm0  = (uint32_t)__cvta_generic_to_shared(smB);
    const uint32_t qh_s = sm0;
    const uint32_t ql_s = sm0 + QTILE * 2;
    const uint32_t kh_s = sm0 + OFF_KV * 2;
    const uint32_t kl_s = kh_s + 2 * KTILE * 2;
    const uint32_t vh_s = kl_s + 2 * KTILE * 2;
    const uint32_t vl_s = vh_s + 2 * KTILE * 2;

    // QK B frags (non-trans)
    const int keyc = wc * 32 + ((lane >> 4) & 1) * 8 + (lane & 7);
    const int dsel = ((lane >> 3) & 1) * 8;
    const uint32_t koff = (uint32_t)(keyc * LDK + dsel) * 2;
    // PV B frags (trans)
    const int vkeyc = wc * 32 + ((lane >> 3) & 1) * 8 + (lane & 7);
    const int vdsel = ((lane >> 4) & 1) * 8;
    const uint32_t voff = (uint32_t)(vkeyc * LDK + vdsel) * 2;
    // Q A frags (non-trans)
    const uint32_t qoff =
        (uint32_t)((wr * 16 + ((lane >> 3) & 1) * 8 + (lane & 7)) * LDK +
                   ((lane >> 4) & 1) * 8) * 2;

    // ---- cp.async loader mapping: thread -> (tensor, row) -------------------
    const int tsel = tid >> 6;          // 0..3 : KH,KL,VH,VL
    const int lrow = tid & 63;
    const __nv_bfloat16* gKV =
        (tsel == 0 ? KHg : tsel == 1 ? KLg : tsel == 2 ? VHg : VLg) +
        bh * SS * DD + (size_t)lrow * DD;
    const uint32_t dst0 = sm0 + (uint32_t)(OFF_KV + tsel * 2 * KTILE) * 2 +
                          (uint32_t)lrow * (LDK * 2);

    float oacc[8][4];
    #pragma unroll
    for (int dt = 0; dt < 8; dt++)
        #pragma unroll
        for (int j = 0; j < 4; j++) oacc[dt][j] = 0.0f;
    float rs[2] = {0.0f, 0.0f};

    // prologue: issue tile 0
    {
        const __nv_bfloat16* src = gKV;
        #pragma unroll
        for (int c = 0; c < 8; c++) cpa16(dst0 + c * 16, src + c * 8);
        asm volatile("cp.async.commit_group;\n");
    }

    const int rA = wr * 16 + gID;
    const int rB = rA + 8;

    for (int t = 0; t < NTILES; t++) {
        if (t + 1 < NTILES) {
            const __nv_bfloat16* src = gKV + (size_t)(t + 1) * BC * DD;
            const uint32_t dst = dst0 + (uint32_t)((t + 1) & 1) * (KTILE * 2);
            #pragma unroll
            for (int c = 0; c < 8; c++) cpa16(dst + c * 16, src + c * 8);
            asm volatile("cp.async.commit_group;\n");
            asm volatile("cp.async.wait_group 1;\n");
        } else {
            asm volatile("cp.async.wait_group 0;\n");
        }
        __syncthreads();

        const uint32_t bufB = (uint32_t)(t & 1) * (KTILE * 2);
        const int key0 = t * BC;

        // ---- S = (Q/8) K^T : 3-term split-bf16 -----------------------------
        float sacc[4][4];
        #pragma unroll
        for (int nt = 0; nt < 4; nt++)
            #pragma unroll
            for (int j = 0; j < 4; j++) sacc[nt][j] = 0.0f;

        #pragma unroll
        for (int ks = 0; ks < 4; ks++) {
            uint32_t qhf[4], qlf[4];
            ldsm4(qhf[0], qhf[1], qhf[2], qhf[3], qh_s + qoff + ks * 32);
            ldsm4(qlf[0], qlf[1], qlf[2], qlf[3], ql_s + qoff + ks * 32);
            uint32_t Bh[4][2], Bl[4][2];
            #pragma unroll
            for (int p = 0; p < 2; p++) {
                uint32_t off = bufB + koff + (uint32_t)((p * 16 * LDK + ks * 16) * 2);
                ldsm4(Bh[2 * p][0], Bh[2 * p][1], Bh[2 * p + 1][0], Bh[2 * p + 1][1],
                      kh_s + off);
                ldsm4(Bl[2 * p][0], Bl[2 * p][1], Bl[2 * p + 1][0], Bl[2 * p + 1][1],
                      kl_s + off);
            }
            #pragma unroll
            for (int nt = 0; nt < 4; nt++) {
                mma16816(sacc[nt], qhf, Bh[nt]);
                mma16816(sacc[nt], qhf, Bl[nt]);
                mma16816(sacc[nt], qlf, Bh[nt]);
            }
        }

        // ---- g prefetch (L2-resident) --------------------------------------
        float2 gA[4], gB[4];
        #pragma unroll
        for (int nt = 0; nt < 4; nt++) {
            const int cg = key0 + wc * 32 + nt * 8 + tig * 2;
            gA[nt] = *(const float2*)(gp + (size_t)rA * SS + cg);
            gB[nt] = *(const float2*)(gp + (size_t)rB * SS + cg);
        }

        // ---- p = exp(|s*g|); store unnormalized attn; pack P hi/lo ---------
        uint32_t ph[2][4], pl[2][4];
        #pragma unroll
        for (int nt = 0; nt < 4; nt++) {
            const int cg = key0 + wc * 32 + nt * 8 + tig * 2;
            float p0 = __expf(fabsf(sacc[nt][0] * gA[nt].x));
            float p1 = __expf(fabsf(sacc[nt][1] * gA[nt].y));
            float p2 = __expf(fabsf(sacc[nt][2] * gB[nt].x));
            float p3 = __expf(fabsf(sacc[nt][3] * gB[nt].y));
            *(float2*)(attnp + (size_t)rA * SS + cg) = make_float2(p0, p1);
            *(float2*)(attnp + (size_t)rB * SS + cg) = make_float2(p2, p3);
            rs[0] += p0 + p1;
            rs[1] += p2 + p3;
            __nv_bfloat16 b0 = __float2bfloat16_rn(p0), b1 = __float2bfloat16_rn(p1);
            __nv_bfloat16 b2 = __float2bfloat16_rn(p2), b3 = __float2bfloat16_rn(p3);
            const int kt = nt >> 1, hf = nt & 1;
            ph[kt][hf * 2 + 0] = pk(b0, b1);
            ph[kt][hf * 2 + 1] = pk(b2, b3);
            pl[kt][hf * 2 + 0] = pk(__float2bfloat16_rn(p0 - __bfloat162float(b0)),
                                    __float2bfloat16_rn(p1 - __bfloat162float(b1)));
            pl[kt][hf * 2 + 1] = pk(__float2bfloat16_rn(p2 - __bfloat162float(b2)),
                                    __float2bfloat16_rn(p3 - __bfloat162float(b3)));
        }

        // ---- O += P V over this warp's 32 keys, 3-term split-bf16 ----------
        #pragma unroll
        for (int kt = 0; kt < 2; kt++) {
            #pragma unroll
            for (int dp = 0; dp < 4; dp++) {
                uint32_t off = bufB + voff + (uint32_t)((kt * 16 * LDK + dp * 16) * 2);
                uint32_t Vh0[2], Vh1[2], Vl0[2], Vl1[2];
                ldsm4t(Vh0[0], Vh0[1], Vh1[0], Vh1[1], vh_s + off);
                ldsm4t(Vl0[0], Vl0[1], Vl1[0], Vl1[1], vl_s + off);
                mma16816(oacc[2 * dp], ph[kt], Vh0);
                mma16816(oacc[2 * dp], ph[kt], Vl0);
                mma16816(oacc[2 * dp], pl[kt], Vh0);
                mma16816(oacc[2 * dp + 1], ph[kt], Vh1);
                mma16816(oacc[2 * dp + 1], ph[kt], Vl1);
                mma16816(oacc[2 * dp + 1], pl[kt], Vh1);
            }
        }

        __syncthreads();
    }

    // ---- epilogue: combine 2 key-half partials, rowsums, normalize ---------
    float* Ob       = (float*)smem_raw;      // [2][64][68]
    float* rowSumSm = Ob + 2 * 64 * 68;
    float* invS     = rowSumSm + 64;

    if (tid < BR) rowSumSm[tid] = 0.0f;
    __syncthreads();

    rs[0] += __shfl_xor_sync(0xffffffffu, rs[0], 1);
    rs[0] += __shfl_xor_sync(0xffffffffu, rs[0], 2);
    rs[1] += __shfl_xor_sync(0xffffffffu, rs[1], 1);
    rs[1] += __shfl_xor_sync(0xffffffffu, rs[1], 2);
    if (tig == 0) {
        atomicAdd(&rowSumSm[rA], rs[0]);
        atomicAdd(&rowSumSm[rB], rs[1]);
    }

    {
        float* ObW = Ob + wc * (64 * 68);
        #pragma unroll
        for (int dt = 0; dt < 8; dt++) {
            const int c = dt * 8 + tig * 2;
            *(float2*)&ObW[rA * 68 + c] = make_float2(oacc[dt][0], oacc[dt][1]);
            *(float2*)&ObW[rB * 68 + c] = make_float2(oacc[dt][2], oacc[dt][3]);
        }
    }
    __syncthreads();

    if (tid < BR) invS[tid] = 1.0f / rowSumSm[tid];
    __syncthreads();

    for (int i = tid; i < BR * DD; i += NTHREADS) {
        const int r = i >> 6, c = i & 63;
        float o = Ob[r * 68 + c] + Ob[64 * 68 + r * 68 + c];
        outp[(size_t)r * DD + c] = o * invS[r];
    }

    // rescale this CTA's attn slice in place (mostly L2-resident)
    for (int i = tid; i < BR * (SS / 4); i += NTHREADS) {
        const int r  = i >> 9;
        const int c4 = (i & 511) << 2;
        float4* p4 = (float4*)(attnp + (size_t)r * SS + c4);
        float4 vv = *p4;
        const float inv = invS[r];
        vv.x *= inv; vv.y *= inv; vv.z *= inv; vv.w *= inv;
        *p4 = vv;
    }
}

// ---------------------------------------------------------------------------
extern "C" void kernel_launch(void* const* d_in, const int* in_sizes, int n_in,
                              void* d_out, int out_size)
{
    const float* q     = (const float*)d_in[0];
    const float* k     = (const float*)d_in[1];
    const float* v     = (const float*)d_in[2];
    const float* dwm   = (const float*)d_in[3];
    const float* sigma = (const float*)d_in[4];

    float* out  = (float*)d_out;                       // [B,H,S,D]
    float* attn = out + (size_t)BB * HH * SS * DD;     // [B,H,S,S]

    g_kernel<<<4096, 256>>>(dwm, sigma, (BB * SS * SS) / 4);
    kvsplit_kernel<<<2048, 256>>>(k, v, (int)(KVELEMS / 4));

    cudaFuncSetAttribute(attn_kernel, cudaFuncAttributeMaxDynamicSharedMemorySize,
                         SMEM_BYTES);
    dim3 grid(SS / BR, HH, BB);
    attn_kernel<<<grid, NTHREADS, SMEM_BYTES>>>(q, out, attn);

    (void)in_sizes; (void)n_in; (void)out_size;
}